// round 5
// baseline (speedup 1.0000x reference)
#include <cuda_runtime.h>
#include <math.h>
#include <stdint.h>

#define CIN  1024
#define HH   32
#define WW   32
#define BB   16
#define HW   1024   // 32*32

#define CKEY 256
#define CVAL 512

// ---------------- scratch (device globals; no allocation allowed) -----------
__device__ float g_mkey[BB * CKEY * HW];          // [b][c][pix]  16.8 MB
__device__ float g_mval[BB * CVAL * HW];          // [b][c][pix]  33.6 MB
__device__ float g_qkey[BB * CKEY * HW];          // [b][c][pix]  16.8 MB
__device__ float g_scores[(size_t)BB * HW * HW];  // [b][q][m]    67 MB

// ---------------------------------------------------------------------------
// fp32 -> tf32 (round to nearest, ties away), result as raw b32 for mma.
// ---------------------------------------------------------------------------
__device__ __forceinline__ uint32_t f2tf32(float f) {
    uint32_t u;
    asm("cvt.rna.tf32.f32 %0, %1;" : "=r"(u) : "f"(f));
    return u;
}

// D(16x8,f32) += A(16x8,tf32,row) * B(8x8,tf32,col)
__device__ __forceinline__ void mma_tf32(float d[4], const uint32_t a[4], const uint32_t b[2]) {
    asm volatile(
        "mma.sync.aligned.m16n8k8.row.col.f32.tf32.tf32.f32 "
        "{%0,%1,%2,%3}, {%4,%5,%6,%7}, {%8,%9}, {%0,%1,%2,%3};"
        : "+f"(d[0]), "+f"(d[1]), "+f"(d[2]), "+f"(d[3])
        : "r"(a[0]), "r"(a[1]), "r"(a[2]), "r"(a[3]), "r"(b[0]), "r"(b[1]));
}

// ---------------------------------------------------------------------------
// Fused 4-conv kernel, tf32 tensor cores. Conv3x3 SAME, C_in=1024.
// grid.x (24 co-tiles): [0,4)->mkey, [4,12)->mval, [12,16)->qkey, [16,24)->out[512..1023]
// Block: 64 out-ch x (4 rows x 32 cols) pixels, 256 threads = 8 warps.
// Warp w: co half wm=w&1 (m32), image row wn=w>>2... w>>1 (n32 = one row of 32 px).
// Per ci-chunk(8) x 9 taps: A frag = W[co32][ci8]@tap, B frag = X[ci8][px32 shifted].
// ---------------------------------------------------------------------------
#define CO_TILE 64
#define CI_TILE 8
#define WS_PITCH 76      // 72 cols padded -> conflict-free A fragment loads
#define XS_PITCH 216     // 6*34=204 padded -> conflict-free B fragment loads

__global__ __launch_bounds__(256, 2) void conv4_tf32_kernel(
    const float* __restrict__ src_temp,    // [B,1024,32,32]
    const float* __restrict__ src_search,  // [B,1024,32,32]
    const float* __restrict__ wk_m, const float* __restrict__ bk_m,
    const float* __restrict__ wv_m, const float* __restrict__ bv_m,
    const float* __restrict__ wk_q, const float* __restrict__ bk_q,
    const float* __restrict__ wv_q, const float* __restrict__ bv_q,
    float* __restrict__ mkey,
    float* __restrict__ mval,
    float* __restrict__ qkey,
    float* __restrict__ outp)              // [B,1024,32,32] final output
{
    __shared__ uint32_t ws_u[CO_TILE * WS_PITCH];   // weights  [co][ci*9+tap] (tf32 bits)
    __shared__ uint32_t xs_u[CI_TILE * XS_PITCH];   // activations [ci][(row 0..5)*34 + col 0..33]

    // ---- block-uniform dispatch ----
    const int gt = blockIdx.x;             // 0..23
    const float* x;  const float* w;  const float* bias;
    float* out;  int c_stride;  int c_offset;  int co0;
    if (gt < 4)        { x = src_temp;   w = wk_m; bias = bk_m; out = mkey; c_stride = CKEY; c_offset = 0;    co0 = gt * CO_TILE; }
    else if (gt < 12)  { x = src_temp;   w = wv_m; bias = bv_m; out = mval; c_stride = CVAL; c_offset = 0;    co0 = (gt - 4) * CO_TILE; }
    else if (gt < 16)  { x = src_search; w = wk_q; bias = bk_q; out = qkey; c_stride = CKEY; c_offset = 0;    co0 = (gt - 12) * CO_TILE; }
    else               { x = src_search; w = wv_q; bias = bv_q; out = outp; c_stride = 1024; c_offset = CVAL; co0 = (gt - 16) * CO_TILE; }

    const int b    = blockIdx.z;
    const int rg   = blockIdx.y;           // image rows rg*4 .. rg*4+3
    const int t    = threadIdx.x;
    const int warp = t >> 5;
    const int lane = t & 31;
    const int gid  = lane >> 2;            // 0..7
    const int ctg  = lane & 3;             // 0..3
    const int wm   = warp & 1;             // co half (m32)
    const int wn   = warp >> 1;            // 0..3 -> image row within group (n32)

    float acc[2][4][4];                    // [m16-tile][n8-tile][frag]
#pragma unroll
    for (int mt = 0; mt < 2; mt++)
#pragma unroll
        for (int j = 0; j < 4; j++)
#pragma unroll
            for (int e = 0; e < 4; e++) acc[mt][j][e] = 0.f;

    const float* xb = x + (size_t)b * CIN * HW;

    for (int ci0 = 0; ci0 < CIN; ci0 += CI_TILE) {
        // --- weights: 64 co x 72 (8ci*9tap) consecutive floats, tf32-converted ---
#pragma unroll 4
        for (int idx = t; idx < CO_TILE * 72; idx += 256) {
            int row = idx / 72;
            int col = idx - row * 72;
            ws_u[row * WS_PITCH + col] =
                f2tf32(w[(size_t)(co0 + row) * (CIN * 9) + (size_t)ci0 * 9 + col]);
        }
        // --- activations: 8 ci x 6 rows x 34 cols (halo, zero-padded), tf32 ---
#pragma unroll 2
        for (int idx = t; idx < CI_TILE * 204; idx += 256) {
            int ci  = idx / 204;
            int rem = idx - ci * 204;
            int rr  = rem / 34;
            int cc  = rem - rr * 34;
            int gh  = rg * 4 - 1 + rr;
            int gw  = cc - 1;
            float v = 0.f;
            if ((unsigned)gh < 32u && (unsigned)gw < 32u)
                v = xb[(size_t)(ci0 + ci) * HW + gh * WW + gw];
            xs_u[ci * XS_PITCH + rr * 34 + cc] = f2tf32(v);
        }
        __syncthreads();

#pragma unroll
        for (int kh = 0; kh < 3; kh++) {
#pragma unroll
            for (int kw = 0; kw < 3; kw++) {
                const int tap = kh * 3 + kw;
                // A fragments: W rows wm*32+mt*16+{gid,gid+8}, k cols {ctg,ctg+4}
                uint32_t a[2][4];
                const uint32_t* wp = ws_u + ctg * 9 + tap;
                const int r0 = wm * 32 + gid;
#pragma unroll
                for (int mt = 0; mt < 2; mt++) {
                    a[mt][0] = wp[(r0 + mt * 16)     * WS_PITCH];
                    a[mt][1] = wp[(r0 + mt * 16 + 8) * WS_PITCH];
                    a[mt][2] = wp[(r0 + mt * 16)     * WS_PITCH + 36]; // (ctg+4)*9 - ctg*9
                    a[mt][3] = wp[(r0 + mt * 16 + 8) * WS_PITCH + 36];
                }
                // B fragments: k rows {ctg,ctg+4}, n cols = pixel j*8+gid (shifted by tap)
                uint32_t bf[4][2];
                const int xoff = (wn + kh) * 34 + kw + gid;
#pragma unroll
                for (int j = 0; j < 4; j++) {
                    bf[j][0] = xs_u[ ctg      * XS_PITCH + xoff + j * 8];
                    bf[j][1] = xs_u[(ctg + 4) * XS_PITCH + xoff + j * 8];
                }
#pragma unroll
                for (int mt = 0; mt < 2; mt++)
#pragma unroll
                    for (int j = 0; j < 4; j++)
                        mma_tf32(acc[mt][j], a[mt], bf[j]);
            }
        }
        __syncthreads();
    }

    // ---- epilogue: bias + store. C frag: (g,2t),(g,2t+1),(g+8,2t),(g+8,2t+1) ----
    const int h = rg * 4 + wn;
#pragma unroll
    for (int mt = 0; mt < 2; mt++) {
        const int co_lo = co0 + wm * 32 + mt * 16 + gid;
        const float b_lo = bias[co_lo];
        const float b_hi = bias[co_lo + 8];
        float* o_lo = out + ((size_t)b * c_stride + c_offset + co_lo)     * HW + h * WW;
        float* o_hi = out + ((size_t)b * c_stride + c_offset + co_lo + 8) * HW + h * WW;
#pragma unroll
        for (int j = 0; j < 4; j++) {
            const int col = j * 8 + ctg * 2;
            o_lo[col]     = acc[mt][j][0] + b_lo;
            o_lo[col + 1] = acc[mt][j][1] + b_lo;
            o_hi[col]     = acc[mt][j][2] + b_hi;
            o_hi[col + 1] = acc[mt][j][3] + b_hi;
        }
    }
}

// ---------------------------------------------------------------------------
// Scores: S[b][q][m] = (1/16) * sum_c qk[b][c][q] * mk[b][c][m]   (fp32, audited)
// ---------------------------------------------------------------------------
__global__ __launch_bounds__(256) void scores_kernel(
    const float* __restrict__ qk,    // [B,256,HW]
    const float* __restrict__ mk,    // [B,256,HW]
    float* __restrict__ s)           // [B,HW,HW] as [b][q][m]
{
    __shared__ float qs[16][64];
    __shared__ float ms[16][64];

    const int b  = blockIdx.z;
    const int q0 = blockIdx.y * 64;
    const int m0 = blockIdx.x * 64;
    const int t  = threadIdx.x;
    const int qsub = t >> 4;
    const int msub = t & 15;

    const float* qb = qk + (size_t)b * CKEY * HW;
    const float* mb = mk + (size_t)b * CKEY * HW;

    float acc[4][4];
#pragma unroll
    for (int i = 0; i < 4; i++)
#pragma unroll
        for (int j = 0; j < 4; j++) acc[i][j] = 0.f;

    for (int c0 = 0; c0 < CKEY; c0 += 16) {
#pragma unroll
        for (int idx = t; idx < 16 * 64; idx += 256) {
            int kk = idx >> 6;
            int e  = idx & 63;
            qs[kk][e] = qb[(size_t)(c0 + kk) * HW + q0 + e];
            ms[kk][e] = mb[(size_t)(c0 + kk) * HW + m0 + e];
        }
        __syncthreads();
#pragma unroll
        for (int kk = 0; kk < 16; kk++) {
            float qv[4], mv[4];
#pragma unroll
            for (int i = 0; i < 4; i++) qv[i] = qs[kk][qsub * 4 + i];
#pragma unroll
            for (int j = 0; j < 4; j++) mv[j] = ms[kk][msub * 4 + j];
#pragma unroll
            for (int i = 0; i < 4; i++)
#pragma unroll
                for (int j = 0; j < 4; j++)
                    acc[i][j] = fmaf(qv[i], mv[j], acc[i][j]);
        }
        __syncthreads();
    }

#pragma unroll
    for (int i = 0; i < 4; i++)
#pragma unroll
        for (int j = 0; j < 4; j++)
            s[((size_t)b * HW + q0 + qsub * 4 + i) * HW + m0 + msub * 4 + j] =
                acc[i][j] * 0.0625f;   // 1/sqrt(256)
}

// ---------------------------------------------------------------------------
// Row softmax over m (audited).
// ---------------------------------------------------------------------------
__global__ __launch_bounds__(256) void softmax_kernel(float* __restrict__ s)
{
    __shared__ float red[8];
    float* p = s + (size_t)blockIdx.x * HW;
    const int t = threadIdx.x;

    float v[4];
    float mx = -INFINITY;
#pragma unroll
    for (int i = 0; i < 4; i++) {
        v[i] = p[t + 256 * i];
        mx = fmaxf(mx, v[i]);
    }
#pragma unroll
    for (int o = 16; o > 0; o >>= 1) mx = fmaxf(mx, __shfl_xor_sync(0xffffffffu, mx, o));
    if ((t & 31) == 0) red[t >> 5] = mx;
    __syncthreads();
    float mall = red[0];
#pragma unroll
    for (int k = 1; k < 8; k++) mall = fmaxf(mall, red[k]);

    float sum = 0.f;
#pragma unroll
    for (int i = 0; i < 4; i++) {
        v[i] = expf(v[i] - mall);
        sum += v[i];
    }
#pragma unroll
    for (int o = 16; o > 0; o >>= 1) sum += __shfl_xor_sync(0xffffffffu, sum, o);
    __syncthreads();
    if ((t & 31) == 0) red[t >> 5] = sum;
    __syncthreads();
    float sall = 0.f;
#pragma unroll
    for (int k = 0; k < 8; k++) sall += red[k];
    float inv = 1.f / sall;
#pragma unroll
    for (int i = 0; i < 4; i++) p[t + 256 * i] = v[i] * inv;
}

// ---------------------------------------------------------------------------
// mem_info: out[b][c][q] = sum_m mv[b][c][m] * S[b][q][m]  (audited)
// ---------------------------------------------------------------------------
__global__ __launch_bounds__(256) void memout_kernel(
    const float* __restrict__ mv,    // [B,512,HW]
    const float* __restrict__ s,     // [B,HW,HW] softmaxed, [b][q][m]
    float* __restrict__ out)         // [B,1024,32,32], channels 0..511
{
    __shared__ float as[64][33];
    __shared__ float bs[64][33];

    const int b  = blockIdx.z;
    const int q0 = blockIdx.y * 64;
    const int c0 = blockIdx.x * 64;
    const int t  = threadIdx.x;
    const int csub = t >> 4;
    const int qsub = t & 15;

    const float* ab = mv + (size_t)b * CVAL * HW;
    const float* sb = s + (size_t)b * HW * HW;

    float acc[4][4];
#pragma unroll
    for (int i = 0; i < 4; i++)
#pragma unroll
        for (int j = 0; j < 4; j++) acc[i][j] = 0.f;

    for (int m0 = 0; m0 < HW; m0 += 32) {
#pragma unroll
        for (int idx = t; idx < 64 * 32; idx += 256) {
            int rr = idx >> 5;
            int kk = idx & 31;
            as[rr][kk] = ab[(size_t)(c0 + rr) * HW + m0 + kk];
            bs[rr][kk] = sb[(size_t)(q0 + rr) * HW + m0 + kk];
        }
        __syncthreads();
#pragma unroll
        for (int kk = 0; kk < 32; kk++) {
            float av[4], bv[4];
#pragma unroll
            for (int i = 0; i < 4; i++) av[i] = as[csub * 4 + i][kk];
#pragma unroll
            for (int j = 0; j < 4; j++) bv[j] = bs[qsub * 4 + j][kk];
#pragma unroll
            for (int i = 0; i < 4; i++)
#pragma unroll
                for (int j = 0; j < 4; j++)
                    acc[i][j] = fmaf(av[i], bv[j], acc[i][j]);
        }
        __syncthreads();
    }

#pragma unroll
    for (int i = 0; i < 4; i++)
#pragma unroll
        for (int j = 0; j < 4; j++)
            out[((size_t)b * 1024 + c0 + csub * 4 + i) * HW + q0 + qsub * 4 + j] = acc[i][j];
}

// ---------------------------------------------------------------------------
extern "C" void kernel_launch(void* const* d_in, const int* in_sizes, int n_in,
                              void* d_out, int out_size)
{
    const float* src_temp   = (const float*)d_in[0];
    const float* src_search = (const float*)d_in[1];
    const float* wk_m = (const float*)d_in[2];
    const float* bk_m = (const float*)d_in[3];
    const float* wv_m = (const float*)d_in[4];
    const float* bv_m = (const float*)d_in[5];
    const float* wk_q = (const float*)d_in[6];
    const float* bk_q = (const float*)d_in[7];
    const float* wv_q = (const float*)d_in[8];
    const float* bv_q = (const float*)d_in[9];
    float* out = (float*)d_out;

    float *p_mkey, *p_mval, *p_qkey, *p_scores;
    cudaGetSymbolAddress((void**)&p_mkey,   g_mkey);
    cudaGetSymbolAddress((void**)&p_mval,   g_mval);
    cudaGetSymbolAddress((void**)&p_qkey,   g_qkey);
    cudaGetSymbolAddress((void**)&p_scores, g_scores);

    dim3 blk(256);

    // all four convs in one tensor-core launch: grid.x = 4 + 8 + 4 + 8 = 24 co-tiles
    conv4_tf32_kernel<<<dim3(24, 8, BB), blk>>>(
        src_temp, src_search,
        wk_m, bk_m, wv_m, bv_m, wk_q, bk_q, wv_q, bv_q,
        p_mkey, p_mval, p_qkey, out);

    // attention (fp32)
    scores_kernel<<<dim3(HW / 64, HW / 64, BB), blk>>>(p_qkey, p_mkey, p_scores);
    softmax_kernel<<<dim3(BB * HW), blk>>>(p_scores);
    memout_kernel<<<dim3(CVAL / 64, HW / 64, BB), blk>>>(p_mval, p_scores, out);
}

// round 11
// speedup vs baseline: 1.4992x; 1.4992x over previous
#include <cuda_runtime.h>
#include <math.h>
#include <stdint.h>

#define CIN  1024
#define HH   32
#define WW   32
#define BB   16
#define HW   1024   // 32*32

#define CKEY 256
#define CVAL 512

// ---------------- scratch (device globals; no allocation allowed) -----------
__device__ float g_mkey[BB * CKEY * HW];          // [b][c][pix]  16.8 MB
__device__ float g_mval[BB * CVAL * HW];          // [b][c][pix]  33.6 MB
__device__ float g_qkey[BB * CKEY * HW];          // [b][c][pix]  16.8 MB
__device__ float g_scores[(size_t)BB * HW * HW];  // [b][q][m]    67 MB

// ---------------------------------------------------------------------------
__device__ __forceinline__ uint32_t f2tf32(float f) {
    uint32_t u;
    asm("cvt.rna.tf32.f32 %0, %1;" : "=r"(u) : "f"(f));
    return u;
}

// D(16x8,f32) += A(16x8,tf32,row) * B(8x8,tf32,col)
// fragment layout (HW-validated in R5):
//   A: a0=A[g][c], a1=A[g+8][c], a2=A[g][c+4], a3=A[g+8][c+4]   (g=lane>>2, c=lane&3)
//   B: b0=B[c][g], b1=B[c+4][g]
//   C: c0=C[g][2c], c1=C[g][2c+1], c2=C[g+8][2c], c3=C[g+8][2c+1]
__device__ __forceinline__ void mma_tf32(float d[4], const uint32_t a[4], const uint32_t b[2]) {
    asm volatile(
        "mma.sync.aligned.m16n8k8.row.col.f32.tf32.tf32.f32 "
        "{%0,%1,%2,%3}, {%4,%5,%6,%7}, {%8,%9}, {%0,%1,%2,%3};"
        : "+f"(d[0]), "+f"(d[1]), "+f"(d[2]), "+f"(d[3])
        : "r"(a[0]), "r"(a[1]), "r"(a[2]), "r"(a[3]), "r"(b[0]), "r"(b[1]));
}

// ---------------------------------------------------------------------------
// Fused 4-conv kernel, tf32 tensor cores. Conv3x3 SAME, C_in=1024.
// grid.x (24 co-tiles): [0,4)->mkey, [4,12)->mval, [12,16)->qkey, [16,24)->out[512..1023]
// Block: 64 out-ch x (8 rows x 32 cols), 256 threads = 8 warps.
// Warp w: image row wn=w, warp tile 64co x 32px (4 mt x 4 j). 1.5 LDS/mma.
// ---------------------------------------------------------------------------
#define CO_TILE 64
#define CI_TILE 8
#define WS_PITCH 76
#define XS_PITCH 344

__global__ __launch_bounds__(256, 2) void conv4_tf32_kernel(
    const float* __restrict__ src_temp,
    const float* __restrict__ src_search,
    const float* __restrict__ wk_m, const float* __restrict__ bk_m,
    const float* __restrict__ wv_m, const float* __restrict__ bv_m,
    const float* __restrict__ wk_q, const float* __restrict__ bk_q,
    const float* __restrict__ wv_q, const float* __restrict__ bv_q,
    float* __restrict__ mkey,
    float* __restrict__ mval,
    float* __restrict__ qkey,
    float* __restrict__ outp)
{
    __shared__ uint32_t ws_u[CO_TILE * WS_PITCH];
    __shared__ uint32_t xs_u[CI_TILE * XS_PITCH];

    const int gt = blockIdx.x;
    const float* x;  const float* w;  const float* bias;
    float* out;  int c_stride;  int c_offset;  int co0;
    if (gt < 4)        { x = src_temp;   w = wk_m; bias = bk_m; out = mkey; c_stride = CKEY; c_offset = 0;    co0 = gt * CO_TILE; }
    else if (gt < 12)  { x = src_temp;   w = wv_m; bias = bv_m; out = mval; c_stride = CVAL; c_offset = 0;    co0 = (gt - 4) * CO_TILE; }
    else if (gt < 16)  { x = src_search; w = wk_q; bias = bk_q; out = qkey; c_stride = CKEY; c_offset = 0;    co0 = (gt - 12) * CO_TILE; }
    else               { x = src_search; w = wv_q; bias = bv_q; out = outp; c_stride = 1024; c_offset = CVAL; co0 = (gt - 16) * CO_TILE; }

    const int b    = blockIdx.z;
    const int rg   = blockIdx.y;
    const int t    = threadIdx.x;
    const int warp = t >> 5;
    const int lane = t & 31;
    const int gid  = lane >> 2;
    const int ctg  = lane & 3;
    const int wn   = warp;

    float acc[4][4][4];
#pragma unroll
    for (int mt = 0; mt < 4; mt++)
#pragma unroll
        for (int j = 0; j < 4; j++)
#pragma unroll
            for (int e = 0; e < 4; e++) acc[mt][j][e] = 0.f;

    const float* xb = x + (size_t)b * CIN * HW;

    for (int ci0 = 0; ci0 < CIN; ci0 += CI_TILE) {
        for (int idx = t; idx < CO_TILE * 72; idx += 256) {
            int row = idx / 72;
            int col = idx - row * 72;
            ws_u[row * WS_PITCH + col] =
                f2tf32(w[(size_t)(co0 + row) * (CIN * 9) + (size_t)ci0 * 9 + col]);
        }
        for (int idx = t; idx < CI_TILE * 340; idx += 256) {
            int ci  = idx / 340;
            int rem = idx - ci * 340;
            int rr  = rem / 34;
            int cc  = rem - rr * 34;
            int gh  = rg * 8 - 1 + rr;
            int gw  = cc - 1;
            float v = 0.f;
            if ((unsigned)gh < 32u && (unsigned)gw < 32u)
                v = xb[(size_t)(ci0 + ci) * HW + gh * WW + gw];
            xs_u[ci * XS_PITCH + rr * 34 + cc] = f2tf32(v);
        }
        __syncthreads();

#pragma unroll
        for (int kh = 0; kh < 3; kh++) {
#pragma unroll
            for (int kw = 0; kw < 3; kw++) {
                const int tap = kh * 3 + kw;
                uint32_t a[4][4];
                const uint32_t* wp = ws_u + ctg * 9 + tap;
#pragma unroll
                for (int mt = 0; mt < 4; mt++) {
                    const int r0 = mt * 16 + gid;
                    a[mt][0] = wp[r0       * WS_PITCH];
                    a[mt][1] = wp[(r0 + 8) * WS_PITCH];
                    a[mt][2] = wp[r0       * WS_PITCH + 36];
                    a[mt][3] = wp[(r0 + 8) * WS_PITCH + 36];
                }
                uint32_t bf[4][2];
                const int xoff = (wn + kh) * 34 + kw + gid;
#pragma unroll
                for (int j = 0; j < 4; j++) {
                    bf[j][0] = xs_u[ ctg      * XS_PITCH + xoff + j * 8];
                    bf[j][1] = xs_u[(ctg + 4) * XS_PITCH + xoff + j * 8];
                }
#pragma unroll
                for (int mt = 0; mt < 4; mt++)
#pragma unroll
                    for (int j = 0; j < 4; j++)
                        mma_tf32(acc[mt][j], a[mt], bf[j]);
            }
        }
        __syncthreads();
    }

    const int h = rg * 8 + wn;
#pragma unroll
    for (int mt = 0; mt < 4; mt++) {
        const int co_lo = co0 + mt * 16 + gid;
        const float b_lo = bias[co_lo];
        const float b_hi = bias[co_lo + 8];
        float* o_lo = out + ((size_t)b * c_stride + c_offset + co_lo)     * HW + h * WW;
        float* o_hi = out + ((size_t)b * c_stride + c_offset + co_lo + 8) * HW + h * WW;
#pragma unroll
        for (int j = 0; j < 4; j++) {
            const int col = j * 8 + ctg * 2;
            o_lo[col]     = acc[mt][j][0] + b_lo;
            o_lo[col + 1] = acc[mt][j][1] + b_lo;
            o_hi[col]     = acc[mt][j][2] + b_hi;
            o_hi[col + 1] = acc[mt][j][3] + b_hi;
        }
    }
}

// ---------------------------------------------------------------------------
// Scores (tf32 mma): S[b][q][m] = (1/16) sum_c qk[b][c][q] * mk[b][c][m]
// M=q, N=m, K=c(256). Block 64q x 64m, warp 16q x 32m. K-chunk 16.
// ---------------------------------------------------------------------------
#define SC_PITCH 72

__global__ __launch_bounds__(256) void scores_tf32_kernel(
    const float* __restrict__ qk,    // [B,256,HW]
    const float* __restrict__ mk,    // [B,256,HW]
    float* __restrict__ s)           // [B,HW,HW] as [b][q][m]
{
    __shared__ uint32_t qs[16 * SC_PITCH];
    __shared__ uint32_t ms[16 * SC_PITCH];

    const int b  = blockIdx.z;
    const int q0 = blockIdx.y * 64;
    const int m0 = blockIdx.x * 64;
    const int t  = threadIdx.x;
    const int warp = t >> 5;
    const int lane = t & 31;
    const int gid  = lane >> 2;
    const int ctg  = lane & 3;
    const int wq   = warp & 3;         // q-tile of 16
    const int wm   = warp >> 2;        // m-half of 32

    const float* qb = qk + (size_t)b * CKEY * HW;
    const float* mb = mk + (size_t)b * CKEY * HW;

    float acc[4][4];
#pragma unroll
    for (int j = 0; j < 4; j++)
#pragma unroll
        for (int e = 0; e < 4; e++) acc[j][e] = 0.f;

    for (int c0 = 0; c0 < CKEY; c0 += 16) {
#pragma unroll
        for (int idx = t; idx < 16 * 64; idx += 256) {
            int kk = idx >> 6;
            int e  = idx & 63;
            qs[kk * SC_PITCH + e] = f2tf32(qb[(size_t)(c0 + kk) * HW + q0 + e]);
            ms[kk * SC_PITCH + e] = f2tf32(mb[(size_t)(c0 + kk) * HW + m0 + e]);
        }
        __syncthreads();
#pragma unroll
        for (int kk0 = 0; kk0 < 16; kk0 += 8) {
            uint32_t a[4];
            a[0] = qs[(kk0 + ctg)     * SC_PITCH + wq * 16 + gid];
            a[1] = qs[(kk0 + ctg)     * SC_PITCH + wq * 16 + gid + 8];
            a[2] = qs[(kk0 + ctg + 4) * SC_PITCH + wq * 16 + gid];
            a[3] = qs[(kk0 + ctg + 4) * SC_PITCH + wq * 16 + gid + 8];
            uint32_t bf[4][2];
#pragma unroll
            for (int j = 0; j < 4; j++) {
                bf[j][0] = ms[(kk0 + ctg)     * SC_PITCH + wm * 32 + j * 8 + gid];
                bf[j][1] = ms[(kk0 + ctg + 4) * SC_PITCH + wm * 32 + j * 8 + gid];
            }
#pragma unroll
            for (int j = 0; j < 4; j++)
                mma_tf32(acc[j], a, bf[j]);
        }
        __syncthreads();
    }

    const int qr = q0 + wq * 16 + gid;
    float* srow_lo = s + ((size_t)b * HW + qr)     * HW + m0 + wm * 32;
    float* srow_hi = s + ((size_t)b * HW + qr + 8) * HW + m0 + wm * 32;
#pragma unroll
    for (int j = 0; j < 4; j++) {
        const int col = j * 8 + ctg * 2;
        srow_lo[col]     = acc[j][0] * 0.0625f;
        srow_lo[col + 1] = acc[j][1] * 0.0625f;
        srow_hi[col]     = acc[j][2] * 0.0625f;
        srow_hi[col + 1] = acc[j][3] * 0.0625f;
    }
}

// ---------------------------------------------------------------------------
// Row softmax over m (fp32, audited).
// ---------------------------------------------------------------------------
__global__ __launch_bounds__(256) void softmax_kernel(float* __restrict__ s)
{
    __shared__ float red[8];
    float* p = s + (size_t)blockIdx.x * HW;
    const int t = threadIdx.x;

    float v[4];
    float mx = -INFINITY;
#pragma unroll
    for (int i = 0; i < 4; i++) {
        v[i] = p[t + 256 * i];
        mx = fmaxf(mx, v[i]);
    }
#pragma unroll
    for (int o = 16; o > 0; o >>= 1) mx = fmaxf(mx, __shfl_xor_sync(0xffffffffu, mx, o));
    if ((t & 31) == 0) red[t >> 5] = mx;
    __syncthreads();
    float mall = red[0];
#pragma unroll
    for (int k = 1; k < 8; k++) mall = fmaxf(mall, red[k]);

    float sum = 0.f;
#pragma unroll
    for (int i = 0; i < 4; i++) {
        v[i] = expf(v[i] - mall);
        sum += v[i];
    }
#pragma unroll
    for (int o = 16; o > 0; o >>= 1) sum += __shfl_xor_sync(0xffffffffu, sum, o);
    __syncthreads();
    if ((t & 31) == 0) red[t >> 5] = sum;
    __syncthreads();
    float sall = 0.f;
#pragma unroll
    for (int k = 0; k < 8; k++) sall += red[k];
    float inv = 1.f / sall;
#pragma unroll
    for (int i = 0; i < 4; i++) p[t + 256 * i] = v[i] * inv;
}

// ---------------------------------------------------------------------------
// mem_info (tf32 mma): out[b][c][q] = sum_m mv[b][c][m] * S[b][q][m]
// M=c(512), N=q(1024), K=m(1024). Block 64c x 128q, warp 32c x 32q. K-chunk 32.
// ---------------------------------------------------------------------------
#define MO_PITCH 36

__global__ __launch_bounds__(256) void memout_tf32_kernel(
    const float* __restrict__ mv,    // [B,512,HW]
    const float* __restrict__ s,     // [B,HW,HW] softmaxed, [b][q][m]
    float* __restrict__ out)         // [B,1024,32,32], channels 0..511
{
    __shared__ uint32_t as2[64 * MO_PITCH];    // [c][m32]
    __shared__ uint32_t ss[128 * MO_PITCH];    // [q][m32]

    const int b  = blockIdx.z;
    const int q0 = blockIdx.y * 128;
    const int c0 = blockIdx.x * 64;
    const int t  = threadIdx.x;
    const int warp = t >> 5;
    const int lane = t & 31;
    const int gid  = lane >> 2;
    const int ctg  = lane & 3;
    const int wc   = warp & 1;         // c-half of 32
    const int wq   = warp >> 1;        // q-quarter of 32

    const float* ab = mv + (size_t)b * CVAL * HW;
    const float* sb = s + (size_t)b * HW * HW;

    float acc[2][4][4];
#pragma unroll
    for (int mt = 0; mt < 2; mt++)
#pragma unroll
        for (int j = 0; j < 4; j++)
#pragma unroll
            for (int e = 0; e < 4; e++) acc[mt][j][e] = 0.f;

    for (int m0 = 0; m0 < HW; m0 += 32) {
#pragma unroll
        for (int idx = t; idx < 64 * 32; idx += 256) {
            int cc = idx >> 5;
            int kk = idx & 31;
            as2[cc * MO_PITCH + kk] = f2tf32(ab[(size_t)(c0 + cc) * HW + m0 + kk]);
        }
#pragma unroll
        for (int idx = t; idx < 128 * 32; idx += 256) {
            int qq = idx >> 5;
            int kk = idx & 31;
            ss[qq * MO_PITCH + kk] = f2tf32(sb[(size_t)(q0 + qq) * HW + m0 + kk]);
        }
        __syncthreads();
#pragma unroll
        for (int kk0 = 0; kk0 < 32; kk0 += 8) {
            uint32_t a[2][4];
#pragma unroll
            for (int mt = 0; mt < 2; mt++) {
                const int r0 = wc * 32 + mt * 16 + gid;
                a[mt][0] = as2[r0       * MO_PITCH + kk0 + ctg];
                a[mt][1] = as2[(r0 + 8) * MO_PITCH + kk0 + ctg];
                a[mt][2] = as2[r0       * MO_PITCH + kk0 + ctg + 4];
                a[mt][3] = as2[(r0 + 8) * MO_PITCH + kk0 + ctg + 4];
            }
            uint32_t bf[4][2];
#pragma unroll
            for (int j = 0; j < 4; j++) {
                const int qn = wq * 32 + j * 8 + gid;
                bf[j][0] = ss[qn * MO_PITCH + kk0 + ctg];
                bf[j][1] = ss[qn * MO_PITCH + kk0 + ctg + 4];
            }
#pragma unroll
            for (int mt = 0; mt < 2; mt++)
#pragma unroll
                for (int j = 0; j < 4; j++)
                    mma_tf32(acc[mt][j], a[mt], bf[j]);
        }
        __syncthreads();
    }

#pragma unroll
    for (int mt = 0; mt < 2; mt++) {
        const int cr = c0 + wc * 32 + mt * 16 + gid;
        float* o_lo = out + ((size_t)b * 1024 + cr)     * HW + q0 + wq * 32;
        float* o_hi = out + ((size_t)b * 1024 + cr + 8) * HW + q0 + wq * 32;
#pragma unroll
        for (int j = 0; j < 4; j++) {
            const int col = j * 8 + ctg * 2;
            o_lo[col]     = acc[mt][j][0];
            o_lo[col + 1] = acc[mt][j][1];
            o_hi[col]     = acc[mt][j][2];
            o_hi[col + 1] = acc[mt][j][3];
        }
    }
}

// ---------------------------------------------------------------------------
extern "C" void kernel_launch(void* const* d_in, const int* in_sizes, int n_in,
                              void* d_out, int out_size)
{
    const float* src_temp   = (const float*)d_in[0];
    const float* src_search = (const float*)d_in[1];
    const float* wk_m = (const float*)d_in[2];
    const float* bk_m = (const float*)d_in[3];
    const float* wv_m = (const float*)d_in[4];
    const float* bv_m = (const float*)d_in[5];
    const float* wk_q = (const float*)d_in[6];
    const float* bk_q = (const float*)d_in[7];
    const float* wv_q = (const float*)d_in[8];
    const float* bv_q = (const float*)d_in[9];
    float* out = (float*)d_out;

    float *p_mkey, *p_mval, *p_qkey, *p_scores;
    cudaGetSymbolAddress((void**)&p_mkey,   g_mkey);
    cudaGetSymbolAddress((void**)&p_mval,   g_mval);
    cudaGetSymbolAddress((void**)&p_qkey,   g_qkey);
    cudaGetSymbolAddress((void**)&p_scores, g_scores);

    dim3 blk(256);

    // all four convs in one tensor-core launch
    conv4_tf32_kernel<<<dim3(24, 4, BB), blk>>>(
        src_temp, src_search,
        wk_m, bk_m, wv_m, bv_m, wk_q, bk_q, wv_q, bv_q,
        p_mkey, p_mval, p_qkey, out);

    // attention (tf32 mma for the two GEMMs, fp32 softmax)
    scores_tf32_kernel<<<dim3(HW / 64, HW / 64, BB), blk>>>(p_qkey, p_mkey, p_scores);
    softmax_kernel<<<dim3(BB * HW), blk>>>(p_scores);
    memout_tf32_kernel<<<dim3(CVAL / 64, HW / 128, BB), blk>>>(p_mval, p_scores, out);
}